// round 8
// baseline (speedup 1.0000x reference)
#include <cuda_runtime.h>
#include <math.h>

#define T_STEPS 4096
#define BATCH   32
#define DIN     256
#define HID     256
#define GATES   1024
#define OUTD    512
#define CL_SZ   8
#define NBLK    128

__device__ float g_xz_f[(size_t)T_STEPS * BATCH * GATES];
__device__ float g_xz_b[(size_t)T_STEPS * BATCH * GATES];
__device__ float g_houts[(size_t)T_STEPS * BATCH * 2 * HID];

__device__ __forceinline__ float sigf(float x)  { return 1.0f / (1.0f + __expf(-x)); }
__device__ __forceinline__ float tanhf_(float x){ return 1.0f - 2.0f / (__expf(2.0f * x) + 1.0f); }

__device__ __forceinline__ unsigned long long ffma2(
    unsigned long long a, unsigned long long b, unsigned long long c) {
    unsigned long long d;
    asm("fma.rn.f32x2 %0, %1, %2, %3;" : "=l"(d) : "l"(a), "l"(b), "l"(c));
    return d;
}
__device__ __forceinline__ unsigned long long bcast2(float a) {
    unsigned long long d;
    asm("mov.b64 %0, {%1, %1};" : "=l"(d) : "f"(a));
    return d;
}
__device__ __forceinline__ unsigned smem_u32(const void* p) {
    return (unsigned)__cvta_generic_to_shared(p);
}
__device__ __forceinline__ void mbar_wait_cl(unsigned addr, unsigned parity) {
    asm volatile(
        "{\n\t.reg .pred P;\n"
        "LW%=:\n\t"
        "mbarrier.try_wait.parity.acquire.cluster.shared::cta.b64 P, [%0], %1, 0x989680;\n\t"
        "@P bra LD%=;\n\t"
        "bra LW%=;\n"
        "LD%=:\n\t}"
        :: "r"(addr), "r"(parity) : "memory");
}

#define CLUSTER_SYNC() do { \
    asm volatile("barrier.cluster.arrive.aligned;" ::: "memory"); \
    asm volatile("barrier.cluster.wait.aligned;"   ::: "memory"); \
} while (0)

// ---------------- GEMM 1: xz = x @ Wx + bias --------------------------------
__global__ void __launch_bounds__(256) k_gemm_xz(
    const float* __restrict__ A, const float* __restrict__ W,
    const float* __restrict__ bias, float* __restrict__ C)
{
    __shared__ float As[8][128];
    __shared__ float Bs[8][128];
    const int tid = threadIdx.x;
    const int n0 = blockIdx.x << 7, m0 = blockIdx.y << 7;
    const int am = tid >> 1, ak = (tid & 1) << 2;
    const int bk = tid >> 5, bn = (tid & 31) << 2;
    const int ty = tid >> 4, tx = tid & 15;
    unsigned long long acc2[8][4] = {};

    for (int k0 = 0; k0 < DIN; k0 += 8) {
        float4 av = *(const float4*)(A + (size_t)(m0 + am) * DIN + k0 + ak);
        float4 bv = *(const float4*)(W + (size_t)(k0 + bk) * GATES + n0 + bn);
        __syncthreads();
        As[ak + 0][am] = av.x; As[ak + 1][am] = av.y;
        As[ak + 2][am] = av.z; As[ak + 3][am] = av.w;
        *(float4*)&Bs[bk][bn] = bv;
        __syncthreads();
#pragma unroll
        for (int kk = 0; kk < 8; kk++) {
            float ar[8];
            *(float4*)&ar[0] = *(const float4*)&As[kk][(ty << 3) + 0];
            *(float4*)&ar[4] = *(const float4*)&As[kk][(ty << 3) + 4];
            union { float4 f; unsigned long long u[2]; } B0, B1;
            B0.f = *(const float4*)&Bs[kk][(tx << 3) + 0];
            B1.f = *(const float4*)&Bs[kk][(tx << 3) + 4];
#pragma unroll
            for (int r = 0; r < 8; r++) {
                unsigned long long a2 = bcast2(ar[r]);
                acc2[r][0] = ffma2(a2, B0.u[0], acc2[r][0]);
                acc2[r][1] = ffma2(a2, B0.u[1], acc2[r][1]);
                acc2[r][2] = ffma2(a2, B1.u[0], acc2[r][2]);
                acc2[r][3] = ffma2(a2, B1.u[1], acc2[r][3]);
            }
        }
    }
    float bi[8];
    *(float4*)&bi[0] = *(const float4*)(bias + n0 + (tx << 3) + 0);
    *(float4*)&bi[4] = *(const float4*)(bias + n0 + (tx << 3) + 4);
#pragma unroll
    for (int r = 0; r < 8; r++) {
        int m = m0 + (ty << 3) + r;
        int t = m & (T_STEPS - 1), b = m >> 12;
        float* dst = C + (size_t)(t * BATCH + b) * GATES + n0 + (tx << 3);
        union { unsigned long long u; float f[2]; } U;
        float o[8];
#pragma unroll
        for (int c4 = 0; c4 < 4; c4++) {
            U.u = acc2[r][c4];
            o[2 * c4 + 0] = U.f[0] + bi[2 * c4 + 0];
            o[2 * c4 + 1] = U.f[1] + bi[2 * c4 + 1];
        }
        *(float4*)(dst + 0) = *(float4*)&o[0];
        *(float4*)(dst + 4) = *(float4*)&o[4];
    }
}

// ---------------- GEMM 2: out = relu(h_cat) @ W_dense + b ------------------
__global__ void __launch_bounds__(256) k_gemm_dense(
    const float* __restrict__ W, const float* __restrict__ bias,
    float* __restrict__ out)
{
    __shared__ float As[8][128];
    __shared__ float Bs[8][128];
    const int tid = threadIdx.x;
    const int n0 = blockIdx.x << 7, m0 = blockIdx.y << 7;
    const int am = tid >> 1, ak = (tid & 1) << 2;
    const int bk = tid >> 5, bn = (tid & 31) << 2;
    const int ty = tid >> 4, tx = tid & 15;
    unsigned long long acc2[8][4] = {};

    for (int k0 = 0; k0 < 2 * HID; k0 += 8) {
        float4 av = *(const float4*)(g_houts + (size_t)(m0 + am) * (2 * HID) + k0 + ak);
        av.x = fmaxf(av.x, 0.f); av.y = fmaxf(av.y, 0.f);
        av.z = fmaxf(av.z, 0.f); av.w = fmaxf(av.w, 0.f);
        float4 bv = *(const float4*)(W + (size_t)(k0 + bk) * OUTD + n0 + bn);
        __syncthreads();
        As[ak + 0][am] = av.x; As[ak + 1][am] = av.y;
        As[ak + 2][am] = av.z; As[ak + 3][am] = av.w;
        *(float4*)&Bs[bk][bn] = bv;
        __syncthreads();
#pragma unroll
        for (int kk = 0; kk < 8; kk++) {
            float ar[8];
            *(float4*)&ar[0] = *(const float4*)&As[kk][(ty << 3) + 0];
            *(float4*)&ar[4] = *(const float4*)&As[kk][(ty << 3) + 4];
            union { float4 f; unsigned long long u[2]; } B0, B1;
            B0.f = *(const float4*)&Bs[kk][(tx << 3) + 0];
            B1.f = *(const float4*)&Bs[kk][(tx << 3) + 4];
#pragma unroll
            for (int r = 0; r < 8; r++) {
                unsigned long long a2 = bcast2(ar[r]);
                acc2[r][0] = ffma2(a2, B0.u[0], acc2[r][0]);
                acc2[r][1] = ffma2(a2, B0.u[1], acc2[r][1]);
                acc2[r][2] = ffma2(a2, B1.u[0], acc2[r][2]);
                acc2[r][3] = ffma2(a2, B1.u[1], acc2[r][3]);
            }
        }
    }
    float bi[8];
    *(float4*)&bi[0] = *(const float4*)(bias + n0 + (tx << 3) + 0);
    *(float4*)&bi[4] = *(const float4*)(bias + n0 + (tx << 3) + 4);
#pragma unroll
    for (int r = 0; r < 8; r++) {
        int m = m0 + (ty << 3) + r;
        int b = m & 31, t = m >> 5;
        float* dst = out + ((size_t)b * T_STEPS + t) * OUTD + n0 + (tx << 3);
        union { unsigned long long u; float f[2]; } U;
        float o[8];
#pragma unroll
        for (int c4 = 0; c4 < 4; c4++) {
            U.u = acc2[r][c4];
            o[2 * c4 + 0] = U.f[0] + bi[2 * c4 + 0];
            o[2 * c4 + 1] = U.f[1] + bi[2 * c4 + 1];
        }
        *(float4*)(dst + 0) = *(float4*)&o[0];
        *(float4*)(dst + 4) = *(float4*)&o[4];
    }
}

// ---------------- Recurrence: mbarrier split-phase exchange ----------------
// Per step: compute -> sync -> producers push h to 7 peers + local store ->
// sync -> 7 lanes send 1 remote mbarrier.arrive each; consumers HW-sleep on
// try_wait parity at next step's top. Terminal CLUSTER_SYNC prevents CTA
// exit while peer remote ops are in flight (round-6 crash).
__global__ void __cluster_dims__(CL_SZ, 1, 1) __launch_bounds__(512, 1) k_recur(
    const float* __restrict__ carry_c, const float* __restrict__ carry_h,
    const float* __restrict__ Wh_f, const float* __restrict__ Wh_b)
{
    __shared__ float h_s[2][2][HID];
    __shared__ float p_s[4][2][128];
    __shared__ unsigned long long mb[2];

    const int tid   = threadIdx.x;
    const int rank  = blockIdx.x & (CL_SZ - 1);
    const int b0    = (blockIdx.x >> 3) << 1;
    const int jbase = rank << 5;

    const int kseg = tid >> 7;
    const int col  = tid & 127;
    const int gate = col >> 5, jl = col & 31;
    const int gc   = (gate << 8) + jbase + jl;
    const int bp = tid >> 5, jp = tid & 31;      // producer map (tid<64)

    h_s[0][tid >> 8][tid & 255] =
        carry_h[(size_t)(b0 + (tid >> 8)) * HID + (tid & 255)];

    if (tid == 0) {
        asm volatile("mbarrier.init.shared.b64 [%0], %1;"
                     :: "r"(smem_u32(&mb[0])), "r"(CL_SZ - 1) : "memory");
        asm volatile("mbarrier.init.shared.b64 [%0], %1;"
                     :: "r"(smem_u32(&mb[1])), "r"(CL_SZ - 1) : "memory");
    }

    float c_reg = 0.f;
    unsigned rem_h[2][CL_SZ];
    if (tid < 64) {
        c_reg = carry_c[(size_t)(b0 + bp) * HID + jbase + jp];
#pragma unroll
        for (int buf = 0; buf < 2; buf++) {
            unsigned loc = smem_u32(&h_s[buf][bp][jbase + jp]);
#pragma unroll
            for (int p = 0; p < CL_SZ; p++)
                asm("mapa.shared::cluster.u32 %0, %1, %2;"
                    : "=r"(rem_h[buf][p]) : "r"(loc), "r"(p));
        }
    }
    unsigned rem_mb[2] = {0u, 0u};
    if (tid >= 64 && tid < 64 + CL_SZ - 1) {
        int l = tid - 64;
        int peer = (l < rank) ? l : l + 1;
#pragma unroll
        for (int i = 0; i < 2; i++)
            asm("mapa.shared::cluster.u32 %0, %1, %2;"
                : "=r"(rem_mb[i]) : "r"(smem_u32(&mb[i])), "r"(peer));
    }
    __syncthreads();
    CLUSTER_SYNC();   // mbars + h bufs visible cluster-wide before step 0

    int gs = 0;
    for (int dir = 0; dir < 2; dir++) {
        const float* __restrict__ Wh = dir ? Wh_b : Wh_f;
        const float* __restrict__ xz = dir ? g_xz_b : g_xz_f;
        const int half = dir ? HID : 0;

        unsigned long long w2[32];
#pragma unroll
        for (int kk = 0; kk < 32; kk++) {
            union { float f[2]; unsigned long long u; } P;
            P.f[0] = Wh[(size_t)((kseg << 6) + 2 * kk + 0) * GATES + gc];
            P.f[1] = Wh[(size_t)((kseg << 6) + 2 * kk + 1) * GATES + gc];
            w2[kk] = P.u;
        }

        float xzp[4];
        if (tid < 64) {
            const int t0 = dir ? (T_STEPS - 1) : 0;
#pragma unroll
            for (int g = 0; g < 4; g++)
                xzp[g] = __ldcg(xz + ((size_t)t0 * BATCH + b0 + bp) * GATES
                                   + (g << 8) + jbase + jp);
        }

        for (int s = 0; s < T_STEPS; s++, gs++) {
            const int t   = dir ? (T_STEPS - 1 - s) : s;
            const int cur = gs & 1, nxt = cur ^ 1;

            if (gs > 0) {
                const int e = gs - 1;
                mbar_wait_cl(smem_u32(&mb[e & 1]), (unsigned)((e >> 1) & 1));
            }

            unsigned long long a0 = 0ull, a1 = 0ull;
            {
                const float4* h0 = (const float4*)&h_s[cur][0][kseg << 6];
                const float4* h1 = (const float4*)&h_s[cur][1][kseg << 6];
#pragma unroll
                for (int q = 0; q < 16; q++) {
                    union { float4 f; unsigned long long u[2]; } U0, U1;
                    U0.f = h0[q]; U1.f = h1[q];
                    a0 = ffma2(U0.u[0], w2[2 * q + 0], a0);
                    a0 = ffma2(U0.u[1], w2[2 * q + 1], a0);
                    a1 = ffma2(U1.u[0], w2[2 * q + 0], a1);
                    a1 = ffma2(U1.u[1], w2[2 * q + 1], a1);
                }
            }
            {
                union { unsigned long long u; float f[2]; } A0, A1;
                A0.u = a0; A1.u = a1;
                p_s[kseg][0][col] = A0.f[0] + A0.f[1];
                p_s[kseg][1][col] = A1.f[0] + A1.f[1];
            }
            __syncthreads();

            if (tid < 64) {
                float z[4];
#pragma unroll
                for (int g = 0; g < 4; g++) {
                    const int cc = (g << 5) + jp;
                    z[g] = xzp[g] + p_s[0][bp][cc] + p_s[1][bp][cc]
                                  + p_s[2][bp][cc] + p_s[3][bp][cc];
                }
                c_reg = fmaf(sigf(z[1]), c_reg, sigf(z[0]) * tanhf_(z[2]));
                const float h = sigf(z[3]) * tanhf_(c_reg);
#pragma unroll
                for (int p = 0; p < CL_SZ; p++) {
                    if (p == rank) continue;
                    asm volatile("st.shared::cluster.f32 [%0], %1;"
                                 :: "r"(rem_h[nxt][p]), "f"(h) : "memory");
                }
                h_s[nxt][bp][jbase + jp] = h;
                g_houts[((size_t)t * BATCH + b0 + bp) * (2 * HID)
                        + half + jbase + jp] = h;
                if (s + 1 < T_STEPS) {
                    const int tn = dir ? (T_STEPS - 2 - s) : (s + 1);
#pragma unroll
                    for (int g = 0; g < 4; g++)
                        xzp[g] = __ldcg(xz + ((size_t)tn * BATCH + b0 + bp) * GATES
                                           + (g << 8) + jbase + jp);
                }
            }
            __syncthreads();   // producer stores happen-before arriving lanes

            if (tid >= 64 && tid < 64 + CL_SZ - 1) {
                asm volatile("fence.acq_rel.cluster;" ::: "memory");
                asm volatile(
                    "mbarrier.arrive.release.cluster.shared::cluster.b64 _, [%0];"
                    :: "r"(rem_mb[gs & 1]) : "memory");
            }
        }
    }
    // Terminal barrier: no CTA may exit while peers' remote DSMEM stores /
    // mbarrier arrives targeting its SMEM are still in flight.
    CLUSTER_SYNC();
}

// ---------------- launch ----------------------------------------------------
extern "C" void kernel_launch(void* const* d_in, const int* in_sizes, int n_in,
                              void* d_out, int out_size) {
    const float* carry_c = (const float*)d_in[0];
    const float* carry_h = (const float*)d_in[1];
    const float* x       = (const float*)d_in[2];
    const float* Wx_f    = (const float*)d_in[3];
    const float* Wh_f    = (const float*)d_in[4];
    const float* b_f     = (const float*)d_in[5];
    const float* Wx_b    = (const float*)d_in[6];
    const float* Wh_b    = (const float*)d_in[7];
    const float* b_b     = (const float*)d_in[8];
    const float* W_dense = (const float*)d_in[9];
    const float* b_dense = (const float*)d_in[10];
    float* out = (float*)d_out;

    float* xz_f; cudaGetSymbolAddress((void**)&xz_f, g_xz_f);
    float* xz_b; cudaGetSymbolAddress((void**)&xz_b, g_xz_b);

    dim3 g1(GATES / 128, (BATCH * T_STEPS) / 128);
    k_gemm_xz<<<g1, 256>>>(x, Wx_f, b_f, xz_f);
    k_gemm_xz<<<g1, 256>>>(x, Wx_b, b_b, xz_b);

    k_recur<<<NBLK, 512>>>(carry_c, carry_h, Wh_f, Wh_b);

    dim3 g2(OUTD / 128, (BATCH * T_STEPS) / 128);
    k_gemm_dense<<<g2, 256>>>(W_dense, b_dense, out);
}

// round 9
// speedup vs baseline: 1.0003x; 1.0003x over previous
#include <cuda_runtime.h>
#include <math.h>

#define T_STEPS 4096
#define BATCH   32
#define DIN     256
#define HID     256
#define GATES   1024
#define OUTD    512
#define CL_SZ   8
#define NBLK    128

__device__ float g_xz_f[(size_t)T_STEPS * BATCH * GATES];
__device__ float g_xz_b[(size_t)T_STEPS * BATCH * GATES];
__device__ float g_houts[(size_t)T_STEPS * BATCH * 2 * HID];

__device__ __forceinline__ float sigf(float x)  { return 1.0f / (1.0f + __expf(-x)); }
__device__ __forceinline__ float tanhf_(float x){ return 1.0f - 2.0f / (__expf(2.0f * x) + 1.0f); }

__device__ __forceinline__ unsigned long long ffma2(
    unsigned long long a, unsigned long long b, unsigned long long c) {
    unsigned long long d;
    asm("fma.rn.f32x2 %0, %1, %2, %3;" : "=l"(d) : "l"(a), "l"(b), "l"(c));
    return d;
}
__device__ __forceinline__ unsigned long long bcast2(float a) {
    unsigned long long d;
    asm("mov.b64 %0, {%1, %1};" : "=l"(d) : "f"(a));
    return d;
}
__device__ __forceinline__ unsigned smem_u32(const void* p) {
    return (unsigned)__cvta_generic_to_shared(p);
}

// Busy wait: poll mbarrier.test_wait, burning independent FFMAs between polls
// to keep the issue pipes (and therefore the DVFS governor) hot.
__device__ __forceinline__ void mbar_wait_busy(unsigned addr, unsigned parity,
                                               float* bf) {
    while (true) {
        unsigned done;
        asm volatile(
            "{\n\t.reg .pred P;\n\t"
            "mbarrier.test_wait.parity.acquire.cluster.shared::cta.b64 P, [%1], %2;\n\t"
            "selp.b32 %0, 1, 0, P;\n\t}"
            : "=r"(done) : "r"(addr), "r"(parity) : "memory");
        if (done) break;
#pragma unroll
        for (int i = 0; i < 8; i++) {
            bf[0] = fmaf(bf[0], 1.0000001f, 1e-7f);
            bf[1] = fmaf(bf[1], 0.9999999f, 1e-7f);
            bf[2] = fmaf(bf[2], 1.0000002f, 1e-7f);
            bf[3] = fmaf(bf[3], 0.9999998f, 1e-7f);
        }
        asm volatile("" :: "f"(bf[0]), "f"(bf[1]), "f"(bf[2]), "f"(bf[3]));
    }
}

#define CLUSTER_SYNC() do { \
    asm volatile("barrier.cluster.arrive.aligned;" ::: "memory"); \
    asm volatile("barrier.cluster.wait.aligned;"   ::: "memory"); \
} while (0)

// ---------------- GEMM 1: xz = x @ Wx + bias --------------------------------
__global__ void __launch_bounds__(256) k_gemm_xz(
    const float* __restrict__ A, const float* __restrict__ W,
    const float* __restrict__ bias, float* __restrict__ C)
{
    __shared__ float As[8][128];
    __shared__ float Bs[8][128];
    const int tid = threadIdx.x;
    const int n0 = blockIdx.x << 7, m0 = blockIdx.y << 7;
    const int am = tid >> 1, ak = (tid & 1) << 2;
    const int bk = tid >> 5, bn = (tid & 31) << 2;
    const int ty = tid >> 4, tx = tid & 15;
    unsigned long long acc2[8][4] = {};

    for (int k0 = 0; k0 < DIN; k0 += 8) {
        float4 av = *(const float4*)(A + (size_t)(m0 + am) * DIN + k0 + ak);
        float4 bv = *(const float4*)(W + (size_t)(k0 + bk) * GATES + n0 + bn);
        __syncthreads();
        As[ak + 0][am] = av.x; As[ak + 1][am] = av.y;
        As[ak + 2][am] = av.z; As[ak + 3][am] = av.w;
        *(float4*)&Bs[bk][bn] = bv;
        __syncthreads();
#pragma unroll
        for (int kk = 0; kk < 8; kk++) {
            float ar[8];
            *(float4*)&ar[0] = *(const float4*)&As[kk][(ty << 3) + 0];
            *(float4*)&ar[4] = *(const float4*)&As[kk][(ty << 3) + 4];
            union { float4 f; unsigned long long u[2]; } B0, B1;
            B0.f = *(const float4*)&Bs[kk][(tx << 3) + 0];
            B1.f = *(const float4*)&Bs[kk][(tx << 3) + 4];
#pragma unroll
            for (int r = 0; r < 8; r++) {
                unsigned long long a2 = bcast2(ar[r]);
                acc2[r][0] = ffma2(a2, B0.u[0], acc2[r][0]);
                acc2[r][1] = ffma2(a2, B0.u[1], acc2[r][1]);
                acc2[r][2] = ffma2(a2, B1.u[0], acc2[r][2]);
                acc2[r][3] = ffma2(a2, B1.u[1], acc2[r][3]);
            }
        }
    }
    float bi[8];
    *(float4*)&bi[0] = *(const float4*)(bias + n0 + (tx << 3) + 0);
    *(float4*)&bi[4] = *(const float4*)(bias + n0 + (tx << 3) + 4);
#pragma unroll
    for (int r = 0; r < 8; r++) {
        int m = m0 + (ty << 3) + r;
        int t = m & (T_STEPS - 1), b = m >> 12;
        float* dst = C + (size_t)(t * BATCH + b) * GATES + n0 + (tx << 3);
        union { unsigned long long u; float f[2]; } U;
        float o[8];
#pragma unroll
        for (int c4 = 0; c4 < 4; c4++) {
            U.u = acc2[r][c4];
            o[2 * c4 + 0] = U.f[0] + bi[2 * c4 + 0];
            o[2 * c4 + 1] = U.f[1] + bi[2 * c4 + 1];
        }
        *(float4*)(dst + 0) = *(float4*)&o[0];
        *(float4*)(dst + 4) = *(float4*)&o[4];
    }
}

// ---------------- GEMM 2: out = relu(h_cat) @ W_dense + b ------------------
__global__ void __launch_bounds__(256) k_gemm_dense(
    const float* __restrict__ W, const float* __restrict__ bias,
    float* __restrict__ out)
{
    __shared__ float As[8][128];
    __shared__ float Bs[8][128];
    const int tid = threadIdx.x;
    const int n0 = blockIdx.x << 7, m0 = blockIdx.y << 7;
    const int am = tid >> 1, ak = (tid & 1) << 2;
    const int bk = tid >> 5, bn = (tid & 31) << 2;
    const int ty = tid >> 4, tx = tid & 15;
    unsigned long long acc2[8][4] = {};

    for (int k0 = 0; k0 < 2 * HID; k0 += 8) {
        float4 av = *(const float4*)(g_houts + (size_t)(m0 + am) * (2 * HID) + k0 + ak);
        av.x = fmaxf(av.x, 0.f); av.y = fmaxf(av.y, 0.f);
        av.z = fmaxf(av.z, 0.f); av.w = fmaxf(av.w, 0.f);
        float4 bv = *(const float4*)(W + (size_t)(k0 + bk) * OUTD + n0 + bn);
        __syncthreads();
        As[ak + 0][am] = av.x; As[ak + 1][am] = av.y;
        As[ak + 2][am] = av.z; As[ak + 3][am] = av.w;
        *(float4*)&Bs[bk][bn] = bv;
        __syncthreads();
#pragma unroll
        for (int kk = 0; kk < 8; kk++) {
            float ar[8];
            *(float4*)&ar[0] = *(const float4*)&As[kk][(ty << 3) + 0];
            *(float4*)&ar[4] = *(const float4*)&As[kk][(ty << 3) + 4];
            union { float4 f; unsigned long long u[2]; } B0, B1;
            B0.f = *(const float4*)&Bs[kk][(tx << 3) + 0];
            B1.f = *(const float4*)&Bs[kk][(tx << 3) + 4];
#pragma unroll
            for (int r = 0; r < 8; r++) {
                unsigned long long a2 = bcast2(ar[r]);
                acc2[r][0] = ffma2(a2, B0.u[0], acc2[r][0]);
                acc2[r][1] = ffma2(a2, B0.u[1], acc2[r][1]);
                acc2[r][2] = ffma2(a2, B1.u[0], acc2[r][2]);
                acc2[r][3] = ffma2(a2, B1.u[1], acc2[r][3]);
            }
        }
    }
    float bi[8];
    *(float4*)&bi[0] = *(const float4*)(bias + n0 + (tx << 3) + 0);
    *(float4*)&bi[4] = *(const float4*)(bias + n0 + (tx << 3) + 4);
#pragma unroll
    for (int r = 0; r < 8; r++) {
        int m = m0 + (ty << 3) + r;
        int b = m & 31, t = m >> 5;
        float* dst = out + ((size_t)b * T_STEPS + t) * OUTD + n0 + (tx << 3);
        union { unsigned long long u; float f[2]; } U;
        float o[8];
#pragma unroll
        for (int c4 = 0; c4 < 4; c4++) {
            U.u = acc2[r][c4];
            o[2 * c4 + 0] = U.f[0] + bi[2 * c4 + 0];
            o[2 * c4 + 1] = U.f[1] + bi[2 * c4 + 1];
        }
        *(float4*)(dst + 0) = *(float4*)&o[0];
        *(float4*)(dst + 4) = *(float4*)&o[4];
    }
}

// ---------------- Recurrence: mbarrier exchange + busy-spin FMA burn -------
// Same protocol as R8 (passing), with: producers moved to warps 14-15 and
// arrive lanes to warp 13 (hi-wid arbiter priority for chain-critical work);
// the sleepy try_wait replaced by test_wait busy-poll with FMA burn so the
// chip never looks idle to the DVFS governor.
__global__ void __cluster_dims__(CL_SZ, 1, 1) __launch_bounds__(512, 1) k_recur(
    const float* __restrict__ carry_c, const float* __restrict__ carry_h,
    const float* __restrict__ Wh_f, const float* __restrict__ Wh_b)
{
    __shared__ float h_s[2][2][HID];
    __shared__ float p_s[4][2][128];
    __shared__ unsigned long long mb[2];

    const int tid   = threadIdx.x;
    const int rank  = blockIdx.x & (CL_SZ - 1);
    const int b0    = (blockIdx.x >> 3) << 1;
    const int jbase = rank << 5;

    const int kseg = tid >> 7;
    const int col  = tid & 127;
    const int gate = col >> 5, jl = col & 31;
    const int gc   = (gate << 8) + jbase + jl;

    // producers: warps 14-15 (tid 448..511)
    const bool isprod = (tid >= 448);
    const int  pt = tid - 448;                 // 0..63
    const int  bp = pt >> 5, jp = pt & 31;
    // arrive lanes: warp 13, tid 416..422
    const bool isarr = (tid >= 416 && tid < 416 + CL_SZ - 1);

    float bf[4] = {1.0f, 1.1f, 0.9f, 1.05f};   // burn registers

    h_s[0][tid >> 8][tid & 255] =
        carry_h[(size_t)(b0 + (tid >> 8)) * HID + (tid & 255)];

    if (tid == 0) {
        asm volatile("mbarrier.init.shared.b64 [%0], %1;"
                     :: "r"(smem_u32(&mb[0])), "r"(CL_SZ - 1) : "memory");
        asm volatile("mbarrier.init.shared.b64 [%0], %1;"
                     :: "r"(smem_u32(&mb[1])), "r"(CL_SZ - 1) : "memory");
    }

    float c_reg = 0.f;
    unsigned rem_h[2][CL_SZ];
    if (isprod) {
        c_reg = carry_c[(size_t)(b0 + bp) * HID + jbase + jp];
#pragma unroll
        for (int buf = 0; buf < 2; buf++) {
            unsigned loc = smem_u32(&h_s[buf][bp][jbase + jp]);
#pragma unroll
            for (int p = 0; p < CL_SZ; p++)
                asm("mapa.shared::cluster.u32 %0, %1, %2;"
                    : "=r"(rem_h[buf][p]) : "r"(loc), "r"(p));
        }
    }
    unsigned rem_mb[2] = {0u, 0u};
    if (isarr) {
        int l = tid - 416;
        int peer = (l < rank) ? l : l + 1;
#pragma unroll
        for (int i = 0; i < 2; i++)
            asm("mapa.shared::cluster.u32 %0, %1, %2;"
                : "=r"(rem_mb[i]) : "r"(smem_u32(&mb[i])), "r"(peer));
    }
    __syncthreads();
    CLUSTER_SYNC();

    int gs = 0;
    for (int dir = 0; dir < 2; dir++) {
        const float* __restrict__ Wh = dir ? Wh_b : Wh_f;
        const float* __restrict__ xz = dir ? g_xz_b : g_xz_f;
        const int half = dir ? HID : 0;

        unsigned long long w2[32];
#pragma unroll
        for (int kk = 0; kk < 32; kk++) {
            union { float f[2]; unsigned long long u; } P;
            P.f[0] = Wh[(size_t)((kseg << 6) + 2 * kk + 0) * GATES + gc];
            P.f[1] = Wh[(size_t)((kseg << 6) + 2 * kk + 1) * GATES + gc];
            w2[kk] = P.u;
        }

        float xzp[4];
        if (isprod) {
            const int t0 = dir ? (T_STEPS - 1) : 0;
#pragma unroll
            for (int g = 0; g < 4; g++)
                xzp[g] = __ldcg(xz + ((size_t)t0 * BATCH + b0 + bp) * GATES
                                   + (g << 8) + jbase + jp);
        }

        for (int s = 0; s < T_STEPS; s++, gs++) {
            const int t   = dir ? (T_STEPS - 1 - s) : s;
            const int cur = gs & 1, nxt = cur ^ 1;

            if (gs > 0) {
                const int e = gs - 1;
                mbar_wait_busy(smem_u32(&mb[e & 1]),
                               (unsigned)((e >> 1) & 1), bf);
            }

            unsigned long long a0 = 0ull, a1 = 0ull;
            {
                const float4* h0 = (const float4*)&h_s[cur][0][kseg << 6];
                const float4* h1 = (const float4*)&h_s[cur][1][kseg << 6];
#pragma unroll
                for (int q = 0; q < 16; q++) {
                    union { float4 f; unsigned long long u[2]; } U0, U1;
                    U0.f = h0[q]; U1.f = h1[q];
                    a0 = ffma2(U0.u[0], w2[2 * q + 0], a0);
                    a0 = ffma2(U0.u[1], w2[2 * q + 1], a0);
                    a1 = ffma2(U1.u[0], w2[2 * q + 0], a1);
                    a1 = ffma2(U1.u[1], w2[2 * q + 1], a1);
                }
            }
            {
                union { unsigned long long u; float f[2]; } A0, A1;
                A0.u = a0; A1.u = a1;
                p_s[kseg][0][col] = A0.f[0] + A0.f[1];
                p_s[kseg][1][col] = A1.f[0] + A1.f[1];
            }
            __syncthreads();

            if (isprod) {
                float z[4];
#pragma unroll
                for (int g = 0; g < 4; g++) {
                    const int cc = (g << 5) + jp;
                    z[g] = xzp[g] + p_s[0][bp][cc] + p_s[1][bp][cc]
                                  + p_s[2][bp][cc] + p_s[3][bp][cc];
                }
                c_reg = fmaf(sigf(z[1]), c_reg, sigf(z[0]) * tanhf_(z[2]));
                const float h = sigf(z[3]) * tanhf_(c_reg);
#pragma unroll
                for (int p = 0; p < CL_SZ; p++) {
                    if (p == rank) continue;
                    asm volatile("st.shared::cluster.f32 [%0], %1;"
                                 :: "r"(rem_h[nxt][p]), "f"(h) : "memory");
                }
                h_s[nxt][bp][jbase + jp] = h;
                g_houts[((size_t)t * BATCH + b0 + bp) * (2 * HID)
                        + half + jbase + jp] = h;
                if (s + 1 < T_STEPS) {
                    const int tn = dir ? (T_STEPS - 2 - s) : (s + 1);
#pragma unroll
                    for (int g = 0; g < 4; g++)
                        xzp[g] = __ldcg(xz + ((size_t)tn * BATCH + b0 + bp) * GATES
                                           + (g << 8) + jbase + jp);
                }
            }
            __syncthreads();   // producer stores happen-before arriving lanes

            if (isarr) {
                asm volatile("fence.acq_rel.cluster;" ::: "memory");
                asm volatile(
                    "mbarrier.arrive.release.cluster.shared::cluster.b64 _, [%0];"
                    :: "r"(rem_mb[gs & 1]) : "memory");
            }
        }
    }
    // keep burn registers observably live (opaque, no codegen)
    asm volatile("" :: "f"(bf[0]), "f"(bf[1]), "f"(bf[2]), "f"(bf[3]));
    CLUSTER_SYNC();   // no CTA exits while peer remote ops are in flight
}

// ---------------- launch ----------------------------------------------------
extern "C" void kernel_launch(void* const* d_in, const int* in_sizes, int n_in,
                              void* d_out, int out_size) {
    const float* carry_c = (const float*)d_in[0];
    const float* carry_h = (const float*)d_in[1];
    const float* x       = (const float*)d_in[2];
    const float* Wx_f    = (const float*)d_in[3];
    const float* Wh_f    = (const float*)d_in[4];
    const float* b_f     = (const float*)d_in[5];
    const float* Wx_b    = (const float*)d_in[6];
    const float* Wh_b    = (const float*)d_in[7];
    const float* b_b     = (const float*)d_in[8];
    const float* W_dense = (const float*)d_in[9];
    const float* b_dense = (const float*)d_in[10];
    float* out = (float*)d_out;

    float* xz_f; cudaGetSymbolAddress((void**)&xz_f, g_xz_f);
    float* xz_b; cudaGetSymbolAddress((void**)&xz_b, g_xz_b);

    dim3 g1(GATES / 128, (BATCH * T_STEPS) / 128);
    k_gemm_xz<<<g1, 256>>>(x, Wx_f, b_f, xz_f);
    k_gemm_xz<<<g1, 256>>>(x, Wx_b, b_b, xz_b);

    k_recur<<<NBLK, 512>>>(carry_c, carry_h, Wh_f, Wh_b);

    dim3 g2(OUTD / 128, (BATCH * T_STEPS) / 128);
    k_gemm_dense<<<g2, 256>>>(W_dense, b_dense, out);
}

// round 10
// speedup vs baseline: 1.5037x; 1.5033x over previous
#include <cuda_runtime.h>
#include <math.h>

#define T_STEPS 4096
#define BATCH   32
#define DIN     256
#define HID     256
#define GATES   1024
#define OUTD    512
#define CL_SZ   8
#define NBLK    128

__device__ float g_xz_f[(size_t)T_STEPS * BATCH * GATES];
__device__ float g_xz_b[(size_t)T_STEPS * BATCH * GATES];
__device__ float g_houts[(size_t)T_STEPS * BATCH * 2 * HID];

__device__ __forceinline__ float sigf(float x)  { return 1.0f / (1.0f + __expf(-x)); }
__device__ __forceinline__ float tanhf_(float x){ return 1.0f - 2.0f / (__expf(2.0f * x) + 1.0f); }

__device__ __forceinline__ unsigned long long ffma2(
    unsigned long long a, unsigned long long b, unsigned long long c) {
    unsigned long long d;
    asm("fma.rn.f32x2 %0, %1, %2, %3;" : "=l"(d) : "l"(a), "l"(b), "l"(c));
    return d;
}
__device__ __forceinline__ unsigned long long bcast2(float a) {
    unsigned long long d;
    asm("mov.b64 %0, {%1, %1};" : "=l"(d) : "f"(a));
    return d;
}
__device__ __forceinline__ unsigned smem_u32(const void* p) {
    return (unsigned)__cvta_generic_to_shared(p);
}
__device__ __forceinline__ void mbar_wait_cl(unsigned addr, unsigned parity) {
    asm volatile(
        "{\n\t.reg .pred P;\n"
        "LW%=:\n\t"
        "mbarrier.try_wait.parity.acquire.cluster.shared::cta.b64 P, [%0], %1, 0x989680;\n\t"
        "@P bra LD%=;\n\t"
        "bra LW%=;\n"
        "LD%=:\n\t}"
        :: "r"(addr), "r"(parity) : "memory");
}

#define CLUSTER_SYNC() do { \
    asm volatile("barrier.cluster.arrive.aligned;" ::: "memory"); \
    asm volatile("barrier.cluster.wait.aligned;"   ::: "memory"); \
} while (0)

// ---------------- GEMM 1: xz = x @ Wx + bias --------------------------------
__global__ void __launch_bounds__(256) k_gemm_xz(
    const float* __restrict__ A, const float* __restrict__ W,
    const float* __restrict__ bias, float* __restrict__ C)
{
    __shared__ float As[8][128];
    __shared__ float Bs[8][128];
    const int tid = threadIdx.x;
    const int n0 = blockIdx.x << 7, m0 = blockIdx.y << 7;
    const int am = tid >> 1, ak = (tid & 1) << 2;
    const int bk = tid >> 5, bn = (tid & 31) << 2;
    const int ty = tid >> 4, tx = tid & 15;
    unsigned long long acc2[8][4] = {};

    for (int k0 = 0; k0 < DIN; k0 += 8) {
        float4 av = *(const float4*)(A + (size_t)(m0 + am) * DIN + k0 + ak);
        float4 bv = *(const float4*)(W + (size_t)(k0 + bk) * GATES + n0 + bn);
        __syncthreads();
        As[ak + 0][am] = av.x; As[ak + 1][am] = av.y;
        As[ak + 2][am] = av.z; As[ak + 3][am] = av.w;
        *(float4*)&Bs[bk][bn] = bv;
        __syncthreads();
#pragma unroll
        for (int kk = 0; kk < 8; kk++) {
            float ar[8];
            *(float4*)&ar[0] = *(const float4*)&As[kk][(ty << 3) + 0];
            *(float4*)&ar[4] = *(const float4*)&As[kk][(ty << 3) + 4];
            union { float4 f; unsigned long long u[2]; } B0, B1;
            B0.f = *(const float4*)&Bs[kk][(tx << 3) + 0];
            B1.f = *(const float4*)&Bs[kk][(tx << 3) + 4];
#pragma unroll
            for (int r = 0; r < 8; r++) {
                unsigned long long a2 = bcast2(ar[r]);
                acc2[r][0] = ffma2(a2, B0.u[0], acc2[r][0]);
                acc2[r][1] = ffma2(a2, B0.u[1], acc2[r][1]);
                acc2[r][2] = ffma2(a2, B1.u[0], acc2[r][2]);
                acc2[r][3] = ffma2(a2, B1.u[1], acc2[r][3]);
            }
        }
    }
    float bi[8];
    *(float4*)&bi[0] = *(const float4*)(bias + n0 + (tx << 3) + 0);
    *(float4*)&bi[4] = *(const float4*)(bias + n0 + (tx << 3) + 4);
#pragma unroll
    for (int r = 0; r < 8; r++) {
        int m = m0 + (ty << 3) + r;
        int t = m & (T_STEPS - 1), b = m >> 12;
        float* dst = C + (size_t)(t * BATCH + b) * GATES + n0 + (tx << 3);
        union { unsigned long long u; float f[2]; } U;
        float o[8];
#pragma unroll
        for (int c4 = 0; c4 < 4; c4++) {
            U.u = acc2[r][c4];
            o[2 * c4 + 0] = U.f[0] + bi[2 * c4 + 0];
            o[2 * c4 + 1] = U.f[1] + bi[2 * c4 + 1];
        }
        *(float4*)(dst + 0) = *(float4*)&o[0];
        *(float4*)(dst + 4) = *(float4*)&o[4];
    }
}

// ---------------- GEMM 2: out = relu(h_cat) @ W_dense + b ------------------
__global__ void __launch_bounds__(256) k_gemm_dense(
    const float* __restrict__ W, const float* __restrict__ bias,
    float* __restrict__ out)
{
    __shared__ float As[8][128];
    __shared__ float Bs[8][128];
    const int tid = threadIdx.x;
    const int n0 = blockIdx.x << 7, m0 = blockIdx.y << 7;
    const int am = tid >> 1, ak = (tid & 1) << 2;
    const int bk = tid >> 5, bn = (tid & 31) << 2;
    const int ty = tid >> 4, tx = tid & 15;
    unsigned long long acc2[8][4] = {};

    for (int k0 = 0; k0 < 2 * HID; k0 += 8) {
        float4 av = *(const float4*)(g_houts + (size_t)(m0 + am) * (2 * HID) + k0 + ak);
        av.x = fmaxf(av.x, 0.f); av.y = fmaxf(av.y, 0.f);
        av.z = fmaxf(av.z, 0.f); av.w = fmaxf(av.w, 0.f);
        float4 bv = *(const float4*)(W + (size_t)(k0 + bk) * OUTD + n0 + bn);
        __syncthreads();
        As[ak + 0][am] = av.x; As[ak + 1][am] = av.y;
        As[ak + 2][am] = av.z; As[ak + 3][am] = av.w;
        *(float4*)&Bs[bk][bn] = bv;
        __syncthreads();
#pragma unroll
        for (int kk = 0; kk < 8; kk++) {
            float ar[8];
            *(float4*)&ar[0] = *(const float4*)&As[kk][(ty << 3) + 0];
            *(float4*)&ar[4] = *(const float4*)&As[kk][(ty << 3) + 4];
            union { float4 f; unsigned long long u[2]; } B0, B1;
            B0.f = *(const float4*)&Bs[kk][(tx << 3) + 0];
            B1.f = *(const float4*)&Bs[kk][(tx << 3) + 4];
#pragma unroll
            for (int r = 0; r < 8; r++) {
                unsigned long long a2 = bcast2(ar[r]);
                acc2[r][0] = ffma2(a2, B0.u[0], acc2[r][0]);
                acc2[r][1] = ffma2(a2, B0.u[1], acc2[r][1]);
                acc2[r][2] = ffma2(a2, B1.u[0], acc2[r][2]);
                acc2[r][3] = ffma2(a2, B1.u[1], acc2[r][3]);
            }
        }
    }
    float bi[8];
    *(float4*)&bi[0] = *(const float4*)(bias + n0 + (tx << 3) + 0);
    *(float4*)&bi[4] = *(const float4*)(bias + n0 + (tx << 3) + 4);
#pragma unroll
    for (int r = 0; r < 8; r++) {
        int m = m0 + (ty << 3) + r;
        int b = m & 31, t = m >> 5;
        float* dst = out + ((size_t)b * T_STEPS + t) * OUTD + n0 + (tx << 3);
        union { unsigned long long u; float f[2]; } U;
        float o[8];
#pragma unroll
        for (int c4 = 0; c4 < 4; c4++) {
            U.u = acc2[r][c4];
            o[2 * c4 + 0] = U.f[0] + bi[2 * c4 + 0];
            o[2 * c4 + 1] = U.f[1] + bi[2 * c4 + 1];
        }
        *(float4*)(dst + 0) = *(float4*)&o[0];
        *(float4*)(dst + 4) = *(float4*)&o[4];
    }
}

// ---------------- Recurrence: st.async fused data+signal exchange ----------
// Per step: compute partials -> ONE __syncthreads -> producers (warps 14-15)
// compute gates and st.async h to all 8 CTAs' h_s[nxt]; each st.async
// decrements the target CTA's mbarrier tx-count. One thread per CTA does
// arrive.expect_tx(2048) per step. Consumers try_wait (acquire.cluster) at
// the next step's top. No fence, no arrive lanes, no second syncthreads.
__global__ void __cluster_dims__(CL_SZ, 1, 1) __launch_bounds__(512, 1) k_recur(
    const float* __restrict__ carry_c, const float* __restrict__ carry_h,
    const float* __restrict__ Wh_f, const float* __restrict__ Wh_b)
{
    __shared__ float h_s[2][2][HID];           // ping-pong: 2048 B apart
    __shared__ float p_s[4][2][128];
    __shared__ unsigned long long mb[2];       // 8 B apart

    const int tid   = threadIdx.x;
    const int rank  = blockIdx.x & (CL_SZ - 1);
    const int b0    = (blockIdx.x >> 3) << 1;
    const int jbase = rank << 5;

    const int kseg = tid >> 7;
    const int col  = tid & 127;
    const int gate = col >> 5, jl = col & 31;
    const int gc   = (gate << 8) + jbase + jl;

    const bool isprod = (tid >= 448);          // warps 14-15
    const int  pt = tid - 448;
    const int  bp = pt >> 5, jp = pt & 31;
    const unsigned TXB = CL_SZ * 64u * 4u;     // 2048 bytes per exchange

    h_s[0][tid >> 8][tid & 255] =
        carry_h[(size_t)(b0 + (tid >> 8)) * HID + (tid & 255)];

    if (tid == 0) {
        asm volatile("mbarrier.init.shared.b64 [%0], %1;"
                     :: "r"(smem_u32(&mb[0])), "r"(1) : "memory");
        asm volatile("mbarrier.init.shared.b64 [%0], %1;"
                     :: "r"(smem_u32(&mb[1])), "r"(1) : "memory");
    }

    float c_reg = 0.f;
    unsigned rem_h0[CL_SZ];   // peer addr of h_s[0][bp][jbase+jp]; buf1 = +2048
    unsigned rem_mb0[CL_SZ];  // peer addr of mb[0]; mb[1] = +8
    if (isprod) {
        c_reg = carry_c[(size_t)(b0 + bp) * HID + jbase + jp];
        unsigned lh = smem_u32(&h_s[0][bp][jbase + jp]);
        unsigned lm = smem_u32(&mb[0]);
#pragma unroll
        for (int p = 0; p < CL_SZ; p++) {
            asm("mapa.shared::cluster.u32 %0, %1, %2;"
                : "=r"(rem_h0[p]) : "r"(lh), "r"(p));
            asm("mapa.shared::cluster.u32 %0, %1, %2;"
                : "=r"(rem_mb0[p]) : "r"(lm), "r"(p));
        }
    }
    __syncthreads();
    CLUSTER_SYNC();   // mbars + h bufs visible cluster-wide before step 0

    int gs = 0;
    for (int dir = 0; dir < 2; dir++) {
        const float* __restrict__ Wh = dir ? Wh_b : Wh_f;
        const float* __restrict__ xz = dir ? g_xz_b : g_xz_f;
        const int half = dir ? HID : 0;

        unsigned long long w2[32];
#pragma unroll
        for (int kk = 0; kk < 32; kk++) {
            union { float f[2]; unsigned long long u; } P;
            P.f[0] = Wh[(size_t)((kseg << 6) + 2 * kk + 0) * GATES + gc];
            P.f[1] = Wh[(size_t)((kseg << 6) + 2 * kk + 1) * GATES + gc];
            w2[kk] = P.u;
        }

        float xzp[4];
        if (isprod) {
            const int t0 = dir ? (T_STEPS - 1) : 0;
#pragma unroll
            for (int g = 0; g < 4; g++)
                xzp[g] = __ldcg(xz + ((size_t)t0 * BATCH + b0 + bp) * GATES
                                   + (g << 8) + jbase + jp);
        }

        for (int s = 0; s < T_STEPS; s++, gs++) {
            const int t   = dir ? (T_STEPS - 1 - s) : s;
            const int cur = gs & 1, nxt = cur ^ 1;

            if (gs > 0) {   // wait for exchange gs-1 (all 2048 B landed)
                const int e = gs - 1;
                mbar_wait_cl(smem_u32(&mb[0]) + (unsigned)((e & 1) << 3),
                             (unsigned)((e >> 1) & 1));
            }
            // declare this step's expected exchange bytes (one thread)
            if (tid == 448)
                asm volatile(
                    "mbarrier.arrive.expect_tx.shared.b64 _, [%0], %1;"
                    :: "r"(smem_u32(&mb[0]) + (unsigned)((gs & 1) << 3)),
                       "r"(TXB) : "memory");

            unsigned long long a0 = 0ull, a1 = 0ull;
            {
                const float4* h0 = (const float4*)&h_s[cur][0][kseg << 6];
                const float4* h1 = (const float4*)&h_s[cur][1][kseg << 6];
#pragma unroll
                for (int q = 0; q < 16; q++) {
                    union { float4 f; unsigned long long u[2]; } U0, U1;
                    U0.f = h0[q]; U1.f = h1[q];
                    a0 = ffma2(U0.u[0], w2[2 * q + 0], a0);
                    a0 = ffma2(U0.u[1], w2[2 * q + 1], a0);
                    a1 = ffma2(U1.u[0], w2[2 * q + 0], a1);
                    a1 = ffma2(U1.u[1], w2[2 * q + 1], a1);
                }
            }
            {
                union { unsigned long long u; float f[2]; } A0, A1;
                A0.u = a0; A1.u = a1;
                p_s[kseg][0][col] = A0.f[0] + A0.f[1];
                p_s[kseg][1][col] = A1.f[0] + A1.f[1];
            }
            __syncthreads();

            if (isprod) {
                float z[4];
#pragma unroll
                for (int g = 0; g < 4; g++) {
                    const int cc = (g << 5) + jp;
                    z[g] = xzp[g] + p_s[0][bp][cc] + p_s[1][bp][cc]
                                  + p_s[2][bp][cc] + p_s[3][bp][cc];
                }
                c_reg = fmaf(sigf(z[1]), c_reg, sigf(z[0]) * tanhf_(z[2]));
                const float h = sigf(z[3]) * tanhf_(c_reg);
                const unsigned hoff = (unsigned)(nxt << 11);     // buf stride 2048B
                const unsigned moff = (unsigned)((gs & 1) << 3); // mbar stride 8B
#pragma unroll
                for (int p = 0; p < CL_SZ; p++) {
                    asm volatile(
                        "st.async.shared::cluster.mbarrier::complete_tx::bytes.b32 "
                        "[%0], %1, [%2];"
                        :: "r"(rem_h0[p] + hoff), "r"(__float_as_uint(h)),
                           "r"(rem_mb0[p] + moff) : "memory");
                }
                g_houts[((size_t)t * BATCH + b0 + bp) * (2 * HID)
                        + half + jbase + jp] = h;
                if (s + 1 < T_STEPS) {
                    const int tn = dir ? (T_STEPS - 2 - s) : (s + 1);
#pragma unroll
                    for (int g = 0; g < 4; g++)
                        xzp[g] = __ldcg(xz + ((size_t)tn * BATCH + b0 + bp) * GATES
                                           + (g << 8) + jbase + jp);
                }
            }
            // no second syncthreads: st.async carries data + signal together
        }
    }
    // drain the final exchange so no in-flight st.async targets exiting CTAs
    {
        const int e = 2 * T_STEPS - 1;
        mbar_wait_cl(smem_u32(&mb[0]) + (unsigned)((e & 1) << 3),
                     (unsigned)((e >> 1) & 1));
    }
    CLUSTER_SYNC();
}

// ---------------- launch ----------------------------------------------------
extern "C" void kernel_launch(void* const* d_in, const int* in_sizes, int n_in,
                              void* d_out, int out_size) {
    const float* carry_c = (const float*)d_in[0];
    const float* carry_h = (const float*)d_in[1];
    const float* x       = (const float*)d_in[2];
    const float* Wx_f    = (const float*)d_in[3];
    const float* Wh_f    = (const float*)d_in[4];
    const float* b_f     = (const float*)d_in[5];
    const float* Wx_b    = (const float*)d_in[6];
    const float* Wh_b    = (const float*)d_in[7];
    const float* b_b     = (const float*)d_in[8];
    const float* W_dense = (const float*)d_in[9];
    const float* b_dense = (const float*)d_in[10];
    float* out = (float*)d_out;

    float* xz_f; cudaGetSymbolAddress((void**)&xz_f, g_xz_f);
    float* xz_b; cudaGetSymbolAddress((void**)&xz_b, g_xz_b);

    dim3 g1(GATES / 128, (BATCH * T_STEPS) / 128);
    k_gemm_xz<<<g1, 256>>>(x, Wx_f, b_f, xz_f);
    k_gemm_xz<<<g1, 256>>>(x, Wx_b, b_b, xz_b);

    k_recur<<<NBLK, 512>>>(carry_c, carry_h, Wh_f, Wh_b);

    dim3 g2(OUTD / 128, (BATCH * T_STEPS) / 128);
    k_gemm_dense<<<g2, 256>>>(W_dense, b_dense, out);
}